// round 16
// baseline (speedup 1.0000x reference)
#include <cuda_runtime.h>
#include <cuda_fp16.h>
#include <math.h>
#include <cstdint>

// ---------------------------------------------------------------------------
// StatefulCausalAttention  (B=1, H=16, T=2304=128+2048+128, D=1024, dk=dv=64)
// R16: R15 (fp16 m16n8k16 everywhere) + proj epilogue rewritten: outputs are
//      staged in smem in final fp16 layout (144B-stride rows, conflict-free),
//      then streamed out as fully-coalesced uint4 stores (replaces thousands
//      of scattered STG.16 per CTA). Attn and conv unchanged.
// ---------------------------------------------------------------------------

#define T_TOT 2304
#define D_IN  1024
#define NH    16

// projection outputs (fp16, k-interleaved within 16-blocks)
__device__ __align__(256) __half g_Qf[NH * T_TOT * 64];
__device__ __align__(256) __half g_Kf[NH * T_TOT * 64];
__device__ __align__(256) __half g_VTf[NH * 64 * T_TOT];   // [h][dv][t']

// frag-ordered fp16 operands for projection
__device__ uint4 g_Xf[144 * 32 * 2 * 32];
__device__ uint4 g_Wf[96 * 32 * 8 * 32];

// ============================ helpers ======================================
__device__ __forceinline__ float ex2f_fast(float x) {
    float y; asm("ex2.approx.f32 %0, %1;" : "=f"(y) : "f"(x)); return y;
}
__device__ __forceinline__ void mma16816h(float* c, uint32_t a0, uint32_t a1,
                                          uint32_t a2, uint32_t a3,
                                          uint32_t b0, uint32_t b1) {
    asm("mma.sync.aligned.m16n8k16.row.col.f32.f16.f16.f32 "
        "{%0,%1,%2,%3}, {%4,%5,%6,%7}, {%8,%9}, {%0,%1,%2,%3};"
        : "+f"(c[0]), "+f"(c[1]), "+f"(c[2]), "+f"(c[3])
        : "r"(a0), "r"(a1), "r"(a2), "r"(a3), "r"(b0), "r"(b1));
}
__device__ __forceinline__ uint32_t packh2(float lo, float hi) {
    __half2 h = __floats2half2_rn(lo, hi);
    return *(uint32_t*)&h;
}
__device__ __forceinline__ uint32_t smem_u32(const void* p) {
    uint32_t a;
    asm("{ .reg .u64 t; cvta.to.shared.u64 t, %1; cvt.u32.u64 %0, t; }" : "=r"(a) : "l"(p));
    return a;
}
#define CP_ASYNC16(dst, src) \
    asm volatile("cp.async.cg.shared.global [%0], [%1], 16;" :: "r"(dst), "l"(src))
#define CP_COMMIT() asm volatile("cp.async.commit_group;" ::: "memory")
#define CP_WAIT(n)  asm volatile("cp.async.wait_group %0;" :: "n"(n) : "memory")

// ============================ prep: X + W -> fp16 frag order ===============
__global__ __launch_bounds__(256) void conv_kernel(
    const float* __restrict__ x,
    const float* __restrict__ Wq,  const float* __restrict__ Wk,  const float* __restrict__ Wv,
    const float* __restrict__ Wqs, const float* __restrict__ Wks, const float* __restrict__ Wvs)
{
    const int bid = blockIdx.x;
    const int tid = threadIdx.x;
    if (bid < 1152) {
        int idx = bid * 256 + tid;                 // 0..294911
        int strip = idx >> 11;
        int rem = idx & 2047;
        int c = rem >> 6;
        int t = (rem >> 5) & 1;
        int lane = rem & 31;
        int g = lane >> 2, q2 = (lane & 3) * 2;
        const float* xr = x + (size_t)(strip * 16 + t * 8 + g) * D_IN + c * 32;
        uint4 u;
        u.x = packh2(xr[q2],      xr[q2 + 1]);
        u.y = packh2(xr[8 + q2],  xr[8 + q2 + 1]);
        u.z = packh2(xr[16 + q2], xr[16 + q2 + 1]);
        u.w = packh2(xr[24 + q2], xr[24 + q2 + 1]);
        g_Xf[idx] = u;
    } else {
#pragma unroll
        for (int p = 0; p < 2; ++p) {
            int widx = (bid - 1152) * 512 + p * 256 + tid;   // 0..786431
            int mh = widx >> 13;
            int rem = widx & 8191;
            int c = rem >> 8;
            int lane = rem & 31;
            int g = lane >> 2, q2 = (lane & 3) * 2;
            int ntl = (rem >> 5) & 7;
            int mat = mh >> 4, h = mh & 15;
            const float* W;
            switch (mat) {
                case 0: W = Wq;  break; case 1: W = Wqs; break;
                case 2: W = Wk;  break; case 3: W = Wks; break;
                case 4: W = Wv;  break; default: W = Wvs; break;
            }
            W += (size_t)h * D_IN * 64;
            const int n = ntl * 8 + g, k0 = c * 32;
            uint4 u;
            u.x = packh2(W[(size_t)(k0 + q2) * 64 + n],      W[(size_t)(k0 + q2 + 1) * 64 + n]);
            u.y = packh2(W[(size_t)(k0 + 8 + q2) * 64 + n],  W[(size_t)(k0 + 8 + q2 + 1) * 64 + n]);
            u.z = packh2(W[(size_t)(k0 + 16 + q2) * 64 + n], W[(size_t)(k0 + 16 + q2 + 1) * 64 + n]);
            u.w = packh2(W[(size_t)(k0 + 24 + q2) * 64 + n], W[(size_t)(k0 + 24 + q2 + 1) * 64 + n]);
            g_Wf[widx] = u;
        }
    }
}

// ============================ projection (fp16 mma, 4-stage ring) ==========
// block (h, by): rows by*64..+63, q,k,v fused (N=192). 256 thr, 8 warps:
// mi = warp>>2 (m32), ni = warp&3 (n48). Chunk = 32 k (2 ksteps of k16).
// stage s at s*16384: A 256 uint4 + B 768 uint4; nrm @65536.
// Epilogue: stage Q/K/V tiles in smem (64x72 half each, final layout) then
// stream out 1536 coalesced uint4 (stage buffers are dead by then).
#define PROJ_SMEM (65536 + 768)

__global__ __launch_bounds__(256, 2) void proj_kernel(const float* __restrict__ sf)
{
    extern __shared__ char smc[];
    float* nrm = (float*)(smc + 65536);
    const uint32_t sb = smem_u32(smc);
    const int h  = blockIdx.x;
    const int by = blockIdx.y;                 // 0..35
    const int state = (by < 2 || by >= 34) ? 1 : 0;
    const int tid = threadIdx.x, warp = tid >> 5, lane = tid & 31;
    const int mi = warp >> 2, ni = warp & 3;
    const int g = lane >> 2, qq = lane & 3;
    const int strip0 = by * 4;

    for (int i = tid; i < 192; i += 256) nrm[i] = 0.f;
    __syncthreads();

    float acc[2][6][4];
#pragma unroll
    for (int st = 0; st < 2; ++st)
#pragma unroll
        for (int nt = 0; nt < 6; ++nt)
#pragma unroll
            for (int e = 0; e < 4; ++e) acc[st][nt][e] = 0.f;

    auto issue_stage = [&](int c) {
        const uint32_t sa = sb + (c & 3) * 16384;
#pragma unroll
        for (int i = 0; i < 4; ++i) {
            int slot = tid + i * 256;
            if (slot < 256) {
                const uint4* src = g_Xf + ((size_t)(strip0 + (slot >> 6)) * 32 + c) * 64
                                   + (slot & 63);
                CP_ASYNC16(sa + slot * 16, src);
            } else {
                int s2 = slot - 256;
                int mat = (s2 >> 8) * 2 + state;
                const uint4* src = g_Wf + ((size_t)(mat * 16 + h) * 32 + c) * 256
                                   + (s2 & 255);
                CP_ASYNC16(sa + 4096 + s2 * 16, src);
            }
        }
    };

    issue_stage(0); CP_COMMIT();
    issue_stage(1); CP_COMMIT();
    issue_stage(2); CP_COMMIT();

    for (int c = 0; c < 32; ++c) {
        if (c < 30)       CP_WAIT(2);
        else if (c == 30) CP_WAIT(1);
        else              CP_WAIT(0);
        __syncthreads();    // stage c visible; all warps past compute(c-1)

        const char* sa = smc + (c & 3) * 16384;
        uint4 Af[2][2], Bf[6];
#pragma unroll
        for (int st = 0; st < 2; ++st)
#pragma unroll
            for (int t = 0; t < 2; ++t)
                Af[st][t] = *(const uint4*)(sa + (((mi * 2 + st) * 2 + t) * 32 + lane) * 16);
#pragma unroll
        for (int nt = 0; nt < 6; ++nt)
            Bf[nt] = *(const uint4*)(sa + 4096 + ((ni * 6 + nt) * 32 + lane) * 16);

#pragma unroll
        for (int s = 0; s < 2; ++s) {
#pragma unroll
            for (int st = 0; st < 2; ++st) {
                uint32_t a0 = s ? Af[st][0].z : Af[st][0].x;
                uint32_t a2 = s ? Af[st][0].w : Af[st][0].y;
                uint32_t a1 = s ? Af[st][1].z : Af[st][1].x;
                uint32_t a3 = s ? Af[st][1].w : Af[st][1].y;
#pragma unroll
                for (int nt = 0; nt < 6; ++nt) {
                    uint32_t b0 = s ? Bf[nt].z : Bf[nt].x;
                    uint32_t b1 = s ? Bf[nt].w : Bf[nt].y;
                    mma16816h(acc[st][nt], a0, a1, a2, a3, b0, b1);
                }
            }
        }
        if (c + 3 < 32) { issue_stage(c + 3); CP_COMMIT(); }
    }

    // ---- norm partials ----
#pragma unroll
    for (int st = 0; st < 2; ++st) {
#pragma unroll
        for (int nt = 0; nt < 6; ++nt) {
            int mat = (ni * 6 + nt) >> 3;
            int rl0 = (mi * 2 + st) * 16 + g;
            atomicAdd(&nrm[mat * 64 + rl0],
                      acc[st][nt][0] * acc[st][nt][0] + acc[st][nt][1] * acc[st][nt][1]);
            atomicAdd(&nrm[mat * 64 + rl0 + 8],
                      acc[st][nt][2] * acc[st][nt][2] + acc[st][nt][3] * acc[st][nt][3]);
        }
    }
    __syncthreads();   // nrm ready; stage buffers dead -> reuse as staging

    // ---- scale + stage to smem in FINAL fp16 layouts ----
    // SQ @0, SK @9216, SV @18432: each [64 rows][72 half] (144B row stride)
    const float qs = sf[h] * 1.44269504088896340736f;
#pragma unroll
    for (int st = 0; st < 2; ++st) {
        const int rl0 = (mi * 2 + st) * 16 + g;
#pragma unroll
        for (int nt = 0; nt < 6; ++nt) {
            const int ntg = ni * 6 + nt;
            const int mat = ntg >> 3;
            const int ntl = ntg & 7;
            const float mult = (mat == 0) ? qs : 1.0f;
            float inv0 = mult / fmaxf(sqrtf(nrm[mat * 64 + rl0]),     1e-12f);
            float inv1 = mult / fmaxf(sqrtf(nrm[mat * 64 + rl0 + 8]), 1e-12f);
            float v0 = acc[st][nt][0] * inv0, v1 = acc[st][nt][1] * inv0;
            float v2 = acc[st][nt][2] * inv1, v3 = acc[st][nt][3] * inv1;
            if (mat < 2) {
                __half* dst = (__half*)(smc + mat * 9216);
                int slot = (ntl >> 1) * 16 + (2 * qq + (ntl & 1)) * 2;
                *(uint32_t*)&dst[(rl0    ) * 72 + slot] = packh2(v0, v1);
                *(uint32_t*)&dst[(rl0 + 8) * 72 + slot] = packh2(v2, v3);
            } else {
                __half* SV = (__half*)(smc + 18432);
                const int col = ntl * 8 + qq * 2;
                float vv[4] = {v0, v1, v2, v3};
#pragma unroll
                for (int e = 0; e < 4; ++e) {
                    int cc = col + (e & 1);            // dv
                    int rr = rl0 + (e >> 1) * 8;       // local t
                    int blk = rr >> 4, kk = rr & 15;
                    int pp = kk >> 1, b = kk & 1;
                    int sp = (pp < 4) ? 2 * pp : 2 * (pp - 4) + 1;
                    SV[cc * 72 + blk * 16 + sp * 2 + b] = __float2half_rn(vv[e]);
                }
            }
        }
    }
    __syncthreads();

    // ---- coalesced write-out: 1536 uint4, 6 per thread ----
    const size_t qko = ((size_t)h * T_TOT + by * 64) * 64;
#pragma unroll
    for (int i = 0; i < 6; ++i) {
        int s2 = tid + i * 256;            // 0..1535
        int reg = s2 >> 9, idx = s2 & 511;
        int row = idx >> 3, c4 = idx & 7;
        uint4 v = *(const uint4*)(smc + reg * 9216 + row * 144 + c4 * 16);
        if (reg == 0)
            *(uint4*)&g_Qf[qko + (size_t)row * 64 + c4 * 8] = v;
        else if (reg == 1)
            *(uint4*)&g_Kf[qko + (size_t)row * 64 + c4 * 8] = v;
        else
            *(uint4*)&g_VTf[(size_t)h * 64 * T_TOT + (size_t)row * T_TOT
                            + by * 64 + c4 * 8] = v;
    }
}

// ============================ attention (fp16, pipelined + mask skip) ======
// (unchanged from R15)
#define STAGE_B 18432
#define ATTN_SMEM (3 * STAGE_B)

__global__ __launch_bounds__(256, 2) void attn_kernel(float* __restrict__ out)
{
    extern __shared__ char smc[];
    const uint32_t sb = smem_u32(smc);
    const int L = blockIdx.x;
    const int r = (L < 152) ? L : 439 - L;
    const int h  = r & 15;
    const int it = 17 - (r >> 4);
    const int rb = it * 128;
    const int tid = threadIdx.x;
    const int warp = tid >> 5, lane = tid & 31;
    const int g = lane >> 2, q = lane & 3;
    const int rg0 = rb + warp * 16 + g;
    const int rg_max = rb + warp * 16 + 15;

    uint32_t qa[4][4];
    {
        const __half* Qf = g_Qf + ((size_t)h * T_TOT + rg0) * 64;
#pragma unroll
        for (int ks = 0; ks < 4; ++ks) {
            uint2 lo = *(const uint2*)&Qf[ks * 16 + q * 4];
            uint2 hi = *(const uint2*)&Qf[8 * 64 + ks * 16 + q * 4];
            qa[ks][0] = lo.x;
            qa[ks][1] = hi.x;
            qa[ks][2] = lo.y;
            qa[ks][3] = hi.y;
        }
    }

    float o[8][4];
#pragma unroll
    for (int j = 0; j < 8; ++j)
#pragma unroll
        for (int e = 0; e < 4; ++e) o[j][e] = 0.f;
    float l0 = 0.f, l1 = 0.f;
    float ps[8][4];

    const int jt0 = (it == 17) ? 2 : 0;
    const int jt1 = 2 * it + 1;

    auto tile_active = [&](int jt_) { return jt_ * 64 <= rg_max; };

    auto issue_stage = [&](int jt, int buf) {
        const int cb = jt * 64;
        const uint32_t stb = sb + buf * STAGE_B;
#pragma unroll
        for (int i = 0; i < 4; ++i) {
            int slot = tid + i * 256;
            int arr = slot >> 9;
            int s2 = slot & 511;
            int row = s2 >> 3, ch = s2 & 7;
            const __half* src = (arr == 0)
                ? g_Kf  + ((size_t)h * T_TOT + cb + row) * 64 + ch * 8
                : g_VTf + (size_t)h * 64 * T_TOT + (size_t)row * T_TOT + cb + ch * 8;
            CP_ASYNC16(stb + arr * 9216 + row * 144 + ch * 16, src);
        }
    };

    auto do_S = [&](const char* st) {
#pragma unroll
        for (int j = 0; j < 8; ++j)
#pragma unroll
            for (int e = 0; e < 4; ++e) ps[j][e] = 0.f;
#pragma unroll
        for (int ks = 0; ks < 4; ++ks) {
#pragma unroll
            for (int j = 0; j < 8; ++j) {
                uint2 b = *(const uint2*)(st + (j * 8 + g) * 144 + ks * 32 + q * 8);
                mma16816h(ps[j], qa[ks][0], qa[ks][1], qa[ks][2], qa[ks][3],
                          b.x, b.y);
            }
        }
    };

    auto do_exp = [&](int jt_) {
        const int cb_ = jt_ * 64;
        const bool needMask = (jt_ >= 2 * it);
#pragma unroll
        for (int j = 0; j < 8; ++j) {
            float e0 = ps[j][0], e1 = ps[j][1];
            float e2 = ps[j][2], e3 = ps[j][3];
            if (needMask) {
                int c0 = cb_ + j * 8 + q * 2, c1 = c0 + 1;
                if (c0 > rg0) e0 = -1e30f;
                if (c1 > rg0) e1 = -1e30f;
                if (c0 > rg0 + 8) e2 = -1e30f;
                if (c1 > rg0 + 8) e3 = -1e30f;
            }
            float p0 = ex2f_fast(e0), p1 = ex2f_fast(e1);
            float p2 = ex2f_fast(e2), p3 = ex2f_fast(e3);
            l0 += p0 + p1;
            l1 += p2 + p3;
            ps[j][0] = p0; ps[j][1] = p1; ps[j][2] = p2; ps[j][3] = p3;
        }
    };

    auto do_PV = [&](const char* st) {
        const char* vb = st + 9216;
#pragma unroll
        for (int ks = 0; ks < 4; ++ks) {
            uint32_t a0 = packh2(ps[2 * ks][0],     ps[2 * ks][1]);
            uint32_t a1 = packh2(ps[2 * ks][2],     ps[2 * ks][3]);
            uint32_t a2 = packh2(ps[2 * ks + 1][0], ps[2 * ks + 1][1]);
            uint32_t a3 = packh2(ps[2 * ks + 1][2], ps[2 * ks + 1][3]);
#pragma unroll
            for (int j = 0; j < 8; ++j) {
                uint2 b = *(const uint2*)(vb + (j * 8 + g) * 144 + ks * 32 + q * 8);
                mma16816h(o[j], a0, a1, a2, a3, b.x, b.y);
            }
        }
    };

    issue_stage(jt0, 0);     CP_COMMIT();
    issue_stage(jt0 + 1, 1); CP_COMMIT();
    CP_WAIT(1);
    __syncthreads();
    if (tile_active(jt0)) { do_S(smc); do_exp(jt0); }

    for (int jt = jt0; jt <= jt1; ++jt) {
        const int bufc = (jt - jt0) % 3;
        if (tile_active(jt)) do_PV(smc + bufc * STAGE_B);
        if (jt < jt1) {
            CP_WAIT(0);
            __syncthreads();
            if (jt + 2 <= jt1) {
                issue_stage(jt + 2, (jt + 2 - jt0) % 3);
                CP_COMMIT();
            }
            if (tile_active(jt + 1)) {
                do_S(smc + ((jt + 1 - jt0) % 3) * STAGE_B);
                do_exp(jt + 1);
            }
        }
    }

    l0 += __shfl_xor_sync(0xffffffffu, l0, 1, 4);
    l0 += __shfl_xor_sync(0xffffffffu, l0, 2, 4);
    l1 += __shfl_xor_sync(0xffffffffu, l1, 1, 4);
    l1 += __shfl_xor_sync(0xffffffffu, l1, 2, 4);
    const float inv0 = 1.0f / l0, inv1 = 1.0f / l1;

    float* og = out + ((size_t)h * T_TOT + rg0) * 64;
#pragma unroll
    for (int j = 0; j < 8; ++j) {
        int c = j * 8 + q * 2;
        *(float2*)(og + c)          = make_float2(o[j][0] * inv0, o[j][1] * inv0);
        *(float2*)(og + 8 * 64 + c) = make_float2(o[j][2] * inv1, o[j][3] * inv1);
    }
}

// ---------------------------------------------------------------------------
extern "C" void kernel_launch(void* const* d_in, const int* in_sizes, int n_in,
                              void* d_out, int out_size)
{
    (void)in_sizes; (void)n_in; (void)out_size;
    const float* x   = (const float*)d_in[0];
    const float* Wq  = (const float*)d_in[1];
    const float* Wk  = (const float*)d_in[2];
    const float* Wv  = (const float*)d_in[3];
    const float* Wqs = (const float*)d_in[4];
    const float* Wks = (const float*)d_in[5];
    const float* Wvs = (const float*)d_in[6];
    const float* sf  = (const float*)d_in[7];
    float* out = (float*)d_out;

    cudaFuncSetAttribute(proj_kernel,
                         cudaFuncAttributeMaxDynamicSharedMemorySize, PROJ_SMEM);
    cudaFuncSetAttribute(attn_kernel,
                         cudaFuncAttributeMaxDynamicSharedMemorySize, ATTN_SMEM);

    conv_kernel<<<2688, 256>>>(x, Wq, Wk, Wv, Wqs, Wks, Wvs);
    proj_kernel<<<dim3(16, 36), 256, PROJ_SMEM>>>(sf);
    attn_kernel<<<288, 256, ATTN_SMEM>>>(out);
}

// round 17
// speedup vs baseline: 1.1331x; 1.1331x over previous
#include <cuda_runtime.h>
#include <cuda_fp16.h>
#include <math.h>
#include <cstdint>

// ---------------------------------------------------------------------------
// StatefulCausalAttention  (B=1, H=16, T=2304=128+2048+128, D=1024, dk=dv=64)
// R17: R16 with attention smem row stride 144B -> 160B (40 words == 8 mod 32):
//      removes a 2-way bank conflict on every S/PV B-fragment LDS.64 that the
//      fp16 conversion had silently reintroduced. Everything else unchanged.
// ---------------------------------------------------------------------------

#define T_TOT 2304
#define D_IN  1024
#define NH    16

// projection outputs (fp16, k-interleaved within 16-blocks)
__device__ __align__(256) __half g_Qf[NH * T_TOT * 64];
__device__ __align__(256) __half g_Kf[NH * T_TOT * 64];
__device__ __align__(256) __half g_VTf[NH * 64 * T_TOT];   // [h][dv][t']

// frag-ordered fp16 operands for projection
__device__ uint4 g_Xf[144 * 32 * 2 * 32];
__device__ uint4 g_Wf[96 * 32 * 8 * 32];

// ============================ helpers ======================================
__device__ __forceinline__ float ex2f_fast(float x) {
    float y; asm("ex2.approx.f32 %0, %1;" : "=f"(y) : "f"(x)); return y;
}
__device__ __forceinline__ void mma16816h(float* c, uint32_t a0, uint32_t a1,
                                          uint32_t a2, uint32_t a3,
                                          uint32_t b0, uint32_t b1) {
    asm("mma.sync.aligned.m16n8k16.row.col.f32.f16.f16.f32 "
        "{%0,%1,%2,%3}, {%4,%5,%6,%7}, {%8,%9}, {%0,%1,%2,%3};"
        : "+f"(c[0]), "+f"(c[1]), "+f"(c[2]), "+f"(c[3])
        : "r"(a0), "r"(a1), "r"(a2), "r"(a3), "r"(b0), "r"(b1));
}
__device__ __forceinline__ uint32_t packh2(float lo, float hi) {
    __half2 h = __floats2half2_rn(lo, hi);
    return *(uint32_t*)&h;
}
__device__ __forceinline__ uint32_t smem_u32(const void* p) {
    uint32_t a;
    asm("{ .reg .u64 t; cvta.to.shared.u64 t, %1; cvt.u32.u64 %0, t; }" : "=r"(a) : "l"(p));
    return a;
}
#define CP_ASYNC16(dst, src) \
    asm volatile("cp.async.cg.shared.global [%0], [%1], 16;" :: "r"(dst), "l"(src))
#define CP_COMMIT() asm volatile("cp.async.commit_group;" ::: "memory")
#define CP_WAIT(n)  asm volatile("cp.async.wait_group %0;" :: "n"(n) : "memory")

// ============================ prep: X + W -> fp16 frag order ===============
__global__ __launch_bounds__(256) void conv_kernel(
    const float* __restrict__ x,
    const float* __restrict__ Wq,  const float* __restrict__ Wk,  const float* __restrict__ Wv,
    const float* __restrict__ Wqs, const float* __restrict__ Wks, const float* __restrict__ Wvs)
{
    const int bid = blockIdx.x;
    const int tid = threadIdx.x;
    if (bid < 1152) {
        int idx = bid * 256 + tid;
        int strip = idx >> 11;
        int rem = idx & 2047;
        int c = rem >> 6;
        int t = (rem >> 5) & 1;
        int lane = rem & 31;
        int g = lane >> 2, q2 = (lane & 3) * 2;
        const float* xr = x + (size_t)(strip * 16 + t * 8 + g) * D_IN + c * 32;
        uint4 u;
        u.x = packh2(xr[q2],      xr[q2 + 1]);
        u.y = packh2(xr[8 + q2],  xr[8 + q2 + 1]);
        u.z = packh2(xr[16 + q2], xr[16 + q2 + 1]);
        u.w = packh2(xr[24 + q2], xr[24 + q2 + 1]);
        g_Xf[idx] = u;
    } else {
#pragma unroll
        for (int p = 0; p < 2; ++p) {
            int widx = (bid - 1152) * 512 + p * 256 + tid;
            int mh = widx >> 13;
            int rem = widx & 8191;
            int c = rem >> 8;
            int lane = rem & 31;
            int g = lane >> 2, q2 = (lane & 3) * 2;
            int ntl = (rem >> 5) & 7;
            int mat = mh >> 4, h = mh & 15;
            const float* W;
            switch (mat) {
                case 0: W = Wq;  break; case 1: W = Wqs; break;
                case 2: W = Wk;  break; case 3: W = Wks; break;
                case 4: W = Wv;  break; default: W = Wvs; break;
            }
            W += (size_t)h * D_IN * 64;
            const int n = ntl * 8 + g, k0 = c * 32;
            uint4 u;
            u.x = packh2(W[(size_t)(k0 + q2) * 64 + n],      W[(size_t)(k0 + q2 + 1) * 64 + n]);
            u.y = packh2(W[(size_t)(k0 + 8 + q2) * 64 + n],  W[(size_t)(k0 + 8 + q2 + 1) * 64 + n]);
            u.z = packh2(W[(size_t)(k0 + 16 + q2) * 64 + n], W[(size_t)(k0 + 16 + q2 + 1) * 64 + n]);
            u.w = packh2(W[(size_t)(k0 + 24 + q2) * 64 + n], W[(size_t)(k0 + 24 + q2 + 1) * 64 + n]);
            g_Wf[widx] = u;
        }
    }
}

// ============================ projection (fp16 mma, 4-stage ring) ==========
#define PROJ_SMEM (65536 + 768)

__global__ __launch_bounds__(256, 2) void proj_kernel(const float* __restrict__ sf)
{
    extern __shared__ char smc[];
    float* nrm = (float*)(smc + 65536);
    const uint32_t sb = smem_u32(smc);
    const int h  = blockIdx.x;
    const int by = blockIdx.y;                 // 0..35
    const int state = (by < 2 || by >= 34) ? 1 : 0;
    const int tid = threadIdx.x, warp = tid >> 5, lane = tid & 31;
    const int mi = warp >> 2, ni = warp & 3;
    const int g = lane >> 2, qq = lane & 3;
    const int strip0 = by * 4;

    for (int i = tid; i < 192; i += 256) nrm[i] = 0.f;
    __syncthreads();

    float acc[2][6][4];
#pragma unroll
    for (int st = 0; st < 2; ++st)
#pragma unroll
        for (int nt = 0; nt < 6; ++nt)
#pragma unroll
            for (int e = 0; e < 4; ++e) acc[st][nt][e] = 0.f;

    auto issue_stage = [&](int c) {
        const uint32_t sa = sb + (c & 3) * 16384;
#pragma unroll
        for (int i = 0; i < 4; ++i) {
            int slot = tid + i * 256;
            if (slot < 256) {
                const uint4* src = g_Xf + ((size_t)(strip0 + (slot >> 6)) * 32 + c) * 64
                                   + (slot & 63);
                CP_ASYNC16(sa + slot * 16, src);
            } else {
                int s2 = slot - 256;
                int mat = (s2 >> 8) * 2 + state;
                const uint4* src = g_Wf + ((size_t)(mat * 16 + h) * 32 + c) * 256
                                   + (s2 & 255);
                CP_ASYNC16(sa + 4096 + s2 * 16, src);
            }
        }
    };

    issue_stage(0); CP_COMMIT();
    issue_stage(1); CP_COMMIT();
    issue_stage(2); CP_COMMIT();

    for (int c = 0; c < 32; ++c) {
        if (c < 30)       CP_WAIT(2);
        else if (c == 30) CP_WAIT(1);
        else              CP_WAIT(0);
        __syncthreads();

        const char* sa = smc + (c & 3) * 16384;
        uint4 Af[2][2], Bf[6];
#pragma unroll
        for (int st = 0; st < 2; ++st)
#pragma unroll
            for (int t = 0; t < 2; ++t)
                Af[st][t] = *(const uint4*)(sa + (((mi * 2 + st) * 2 + t) * 32 + lane) * 16);
#pragma unroll
        for (int nt = 0; nt < 6; ++nt)
            Bf[nt] = *(const uint4*)(sa + 4096 + ((ni * 6 + nt) * 32 + lane) * 16);

#pragma unroll
        for (int s = 0; s < 2; ++s) {
#pragma unroll
            for (int st = 0; st < 2; ++st) {
                uint32_t a0 = s ? Af[st][0].z : Af[st][0].x;
                uint32_t a2 = s ? Af[st][0].w : Af[st][0].y;
                uint32_t a1 = s ? Af[st][1].z : Af[st][1].x;
                uint32_t a3 = s ? Af[st][1].w : Af[st][1].y;
#pragma unroll
                for (int nt = 0; nt < 6; ++nt) {
                    uint32_t b0 = s ? Bf[nt].z : Bf[nt].x;
                    uint32_t b1 = s ? Bf[nt].w : Bf[nt].y;
                    mma16816h(acc[st][nt], a0, a1, a2, a3, b0, b1);
                }
            }
        }
        if (c + 3 < 32) { issue_stage(c + 3); CP_COMMIT(); }
    }

    // ---- norm partials ----
#pragma unroll
    for (int st = 0; st < 2; ++st) {
#pragma unroll
        for (int nt = 0; nt < 6; ++nt) {
            int mat = (ni * 6 + nt) >> 3;
            int rl0 = (mi * 2 + st) * 16 + g;
            atomicAdd(&nrm[mat * 64 + rl0],
                      acc[st][nt][0] * acc[st][nt][0] + acc[st][nt][1] * acc[st][nt][1]);
            atomicAdd(&nrm[mat * 64 + rl0 + 8],
                      acc[st][nt][2] * acc[st][nt][2] + acc[st][nt][3] * acc[st][nt][3]);
        }
    }
    __syncthreads();   // nrm ready; stage buffers dead -> reuse as staging

    // ---- scale + stage to smem in FINAL fp16 layouts ----
    const float qs = sf[h] * 1.44269504088896340736f;
#pragma unroll
    for (int st = 0; st < 2; ++st) {
        const int rl0 = (mi * 2 + st) * 16 + g;
#pragma unroll
        for (int nt = 0; nt < 6; ++nt) {
            const int ntg = ni * 6 + nt;
            const int mat = ntg >> 3;
            const int ntl = ntg & 7;
            const float mult = (mat == 0) ? qs : 1.0f;
            float inv0 = mult / fmaxf(sqrtf(nrm[mat * 64 + rl0]),     1e-12f);
            float inv1 = mult / fmaxf(sqrtf(nrm[mat * 64 + rl0 + 8]), 1e-12f);
            float v0 = acc[st][nt][0] * inv0, v1 = acc[st][nt][1] * inv0;
            float v2 = acc[st][nt][2] * inv1, v3 = acc[st][nt][3] * inv1;
            if (mat < 2) {
                __half* dst = (__half*)(smc + mat * 9216);
                int slot = (ntl >> 1) * 16 + (2 * qq + (ntl & 1)) * 2;
                *(uint32_t*)&dst[(rl0    ) * 72 + slot] = packh2(v0, v1);
                *(uint32_t*)&dst[(rl0 + 8) * 72 + slot] = packh2(v2, v3);
            } else {
                __half* SV = (__half*)(smc + 18432);
                const int col = ntl * 8 + qq * 2;
                float vv[4] = {v0, v1, v2, v3};
#pragma unroll
                for (int e = 0; e < 4; ++e) {
                    int cc = col + (e & 1);
                    int rr = rl0 + (e >> 1) * 8;
                    int blk = rr >> 4, kk = rr & 15;
                    int pp = kk >> 1, b = kk & 1;
                    int sp = (pp < 4) ? 2 * pp : 2 * (pp - 4) + 1;
                    SV[cc * 72 + blk * 16 + sp * 2 + b] = __float2half_rn(vv[e]);
                }
            }
        }
    }
    __syncthreads();

    // ---- coalesced write-out: 1536 uint4, 6 per thread ----
    const size_t qko = ((size_t)h * T_TOT + by * 64) * 64;
#pragma unroll
    for (int i = 0; i < 6; ++i) {
        int s2 = tid + i * 256;
        int reg = s2 >> 9, idx = s2 & 511;
        int row = idx >> 3, c4 = idx & 7;
        uint4 v = *(const uint4*)(smc + reg * 9216 + row * 144 + c4 * 16);
        if (reg == 0)
            *(uint4*)&g_Qf[qko + (size_t)row * 64 + c4 * 8] = v;
        else if (reg == 1)
            *(uint4*)&g_Kf[qko + (size_t)row * 64 + c4 * 8] = v;
        else
            *(uint4*)&g_VTf[(size_t)h * 64 * T_TOT + (size_t)row * T_TOT
                            + by * 64 + c4 * 8] = v;
    }
}

// ============================ attention (fp16, 160B stride) ================
// 256 threads, 8 warps x 16 q-rows, kv-tile 64, 2 CTAs/SM, snake schedule.
// 3-stage ring; PV(jt) -> [wait+sync] -> S(jt+1) -> exp(jt+1); mask skip.
// Stage (20480 B): K fp16 [64 rows][160B] @0 ; V fp16 [64 dv][160B] @10240.
// 160B = 40 words == 8 (mod 32): B-frag LDS.64 conflict-free per phase.
#define ROWB 160
#define STAGE_B 20480
#define ATTN_SMEM (3 * STAGE_B)

__global__ __launch_bounds__(256, 2) void attn_kernel(float* __restrict__ out)
{
    extern __shared__ char smc[];
    const uint32_t sb = smem_u32(smc);
    const int L = blockIdx.x;
    const int r = (L < 152) ? L : 439 - L;
    const int h  = r & 15;
    const int it = 17 - (r >> 4);
    const int rb = it * 128;
    const int tid = threadIdx.x;
    const int warp = tid >> 5, lane = tid & 31;
    const int g = lane >> 2, q = lane & 3;
    const int rg0 = rb + warp * 16 + g;
    const int rg_max = rb + warp * 16 + 15;

    uint32_t qa[4][4];
    {
        const __half* Qf = g_Qf + ((size_t)h * T_TOT + rg0) * 64;
#pragma unroll
        for (int ks = 0; ks < 4; ++ks) {
            uint2 lo = *(const uint2*)&Qf[ks * 16 + q * 4];
            uint2 hi = *(const uint2*)&Qf[8 * 64 + ks * 16 + q * 4];
            qa[ks][0] = lo.x;
            qa[ks][1] = hi.x;
            qa[ks][2] = lo.y;
            qa[ks][3] = hi.y;
        }
    }

    float o[8][4];
#pragma unroll
    for (int j = 0; j < 8; ++j)
#pragma unroll
        for (int e = 0; e < 4; ++e) o[j][e] = 0.f;
    float l0 = 0.f, l1 = 0.f;
    float ps[8][4];

    const int jt0 = (it == 17) ? 2 : 0;
    const int jt1 = 2 * it + 1;

    auto tile_active = [&](int jt_) { return jt_ * 64 <= rg_max; };

    auto issue_stage = [&](int jt, int buf) {
        const int cb = jt * 64;
        const uint32_t stb = sb + buf * STAGE_B;
#pragma unroll
        for (int i = 0; i < 4; ++i) {
            int slot = tid + i * 256;
            int arr = slot >> 9;
            int s2 = slot & 511;
            int row = s2 >> 3, ch = s2 & 7;
            const __half* src = (arr == 0)
                ? g_Kf  + ((size_t)h * T_TOT + cb + row) * 64 + ch * 8
                : g_VTf + (size_t)h * 64 * T_TOT + (size_t)row * T_TOT + cb + ch * 8;
            CP_ASYNC16(stb + arr * 10240 + row * ROWB + ch * 16, src);
        }
    };

    auto do_S = [&](const char* st) {
#pragma unroll
        for (int j = 0; j < 8; ++j)
#pragma unroll
            for (int e = 0; e < 4; ++e) ps[j][e] = 0.f;
#pragma unroll
        for (int ks = 0; ks < 4; ++ks) {
#pragma unroll
            for (int j = 0; j < 8; ++j) {
                uint2 b = *(const uint2*)(st + (j * 8 + g) * ROWB + ks * 32 + q * 8);
                mma16816h(ps[j], qa[ks][0], qa[ks][1], qa[ks][2], qa[ks][3],
                          b.x, b.y);
            }
        }
    };

    auto do_exp = [&](int jt_) {
        const int cb_ = jt_ * 64;
        const bool needMask = (jt_ >= 2 * it);
#pragma unroll
        for (int j = 0; j < 8; ++j) {
            float e0 = ps[j][0], e1 = ps[j][1];
            float e2 = ps[j][2], e3 = ps[j][3];
            if (needMask) {
                int c0 = cb_ + j * 8 + q * 2, c1 = c0 + 1;
                if (c0 > rg0) e0 = -1e30f;
                if (c1 > rg0) e1 = -1e30f;
                if (c0 > rg0 + 8) e2 = -1e30f;
                if (c1 > rg0 + 8) e3 = -1e30f;
            }
            float p0 = ex2f_fast(e0), p1 = ex2f_fast(e1);
            float p2 = ex2f_fast(e2), p3 = ex2f_fast(e3);
            l0 += p0 + p1;
            l1 += p2 + p3;
            ps[j][0] = p0; ps[j][1] = p1; ps[j][2] = p2; ps[j][3] = p3;
        }
    };

    auto do_PV = [&](const char* st) {
        const char* vb = st + 10240;
#pragma unroll
        for (int ks = 0; ks < 4; ++ks) {
            uint32_t a0 = packh2(ps[2 * ks][0],     ps[2 * ks][1]);
            uint32_t a1 = packh2(ps[2 * ks][2],     ps[2 * ks][3]);
            uint32_t a2 = packh2(ps[2 * ks + 1][0], ps[2 * ks + 1][1]);
            uint32_t a3 = packh2(ps[2 * ks + 1][2], ps[2 * ks + 1][3]);
#pragma unroll
            for (int j = 0; j < 8; ++j) {
                uint2 b = *(const uint2*)(vb + (j * 8 + g) * ROWB + ks * 32 + q * 8);
                mma16816h(o[j], a0, a1, a2, a3, b.x, b.y);
            }
        }
    };

    issue_stage(jt0, 0);     CP_COMMIT();
    issue_stage(jt0 + 1, 1); CP_COMMIT();
    CP_WAIT(1);
    __syncthreads();
    if (tile_active(jt0)) { do_S(smc); do_exp(jt0); }

    for (int jt = jt0; jt <= jt1; ++jt) {
        const int bufc = (jt - jt0) % 3;
        if (tile_active(jt)) do_PV(smc + bufc * STAGE_B);
        if (jt < jt1) {
            CP_WAIT(0);
            __syncthreads();
            if (jt + 2 <= jt1) {
                issue_stage(jt + 2, (jt + 2 - jt0) % 3);
                CP_COMMIT();
            }
            if (tile_active(jt + 1)) {
                do_S(smc + ((jt + 1 - jt0) % 3) * STAGE_B);
                do_exp(jt + 1);
            }
        }
    }

    l0 += __shfl_xor_sync(0xffffffffu, l0, 1, 4);
    l0 += __shfl_xor_sync(0xffffffffu, l0, 2, 4);
    l1 += __shfl_xor_sync(0xffffffffu, l1, 1, 4);
    l1 += __shfl_xor_sync(0xffffffffu, l1, 2, 4);
    const float inv0 = 1.0f / l0, inv1 = 1.0f / l1;

    float* og = out + ((size_t)h * T_TOT + rg0) * 64;
#pragma unroll
    for (int j = 0; j < 8; ++j) {
        int c = j * 8 + q * 2;
        *(float2*)(og + c)          = make_float2(o[j][0] * inv0, o[j][1] * inv0);
        *(float2*)(og + 8 * 64 + c) = make_float2(o[j][2] * inv1, o[j][3] * inv1);
    }
}

// ---------------------------------------------------------------------------
extern "C" void kernel_launch(void* const* d_in, const int* in_sizes, int n_in,
                              void* d_out, int out_size)
{
    (void)in_sizes; (void)n_in; (void)out_size;
    const float* x   = (const float*)d_in[0];
    const float* Wq  = (const float*)d_in[1];
    const float* Wk  = (const float*)d_in[2];
    const float* Wv  = (const float*)d_in[3];
    const float* Wqs = (const float*)d_in[4];
    const float* Wks = (const float*)d_in[5];
    const float* Wvs = (const float*)d_in[6];
    const float* sf  = (const float*)d_in[7];
    float* out = (float*)d_out;

    cudaFuncSetAttribute(proj_kernel,
                         cudaFuncAttributeMaxDynamicSharedMemorySize, PROJ_SMEM);
    cudaFuncSetAttribute(attn_kernel,
                         cudaFuncAttributeMaxDynamicSharedMemorySize, ATTN_SMEM);

    conv_kernel<<<2688, 256>>>(x, Wq, Wk, Wv, Wqs, Wks, Wvs);
    proj_kernel<<<dim3(16, 36), 256, PROJ_SMEM>>>(sf);
    attn_kernel<<<288, 256, ATTN_SMEM>>>(out);
}